// round 11
// baseline (speedup 1.0000x reference)
#include <cuda_runtime.h>
#include <cstdint>

#define NB_IMG   16
#define NA       22743
#define NCH      85
#define NCLS     80
#define PRE      1000
#define PADN     1024
#define SORTN    4096
#define CAP      32768
#define NBINS    8192
#define MAXDET   300
#define CONF_TH  0.2f
#define NMS_TH   0.45f
#define SBUF     2048

static __device__ __constant__ unsigned B09 = 0x3F666666u; // bits(0.9f)

__device__ unsigned            g_hist[NB_IMG][NBINS];     // zero-init; re-zeroed by k_all
__device__ unsigned            g_candcnt[NB_IMG];         // idem
__device__ unsigned long long  g_cand[NB_IMG][CAP];

// ---------------------------------------------------------------- scan
// Phase A: block-compact hot anchors (conf>0.9).  Phase B: one warp per hot
// anchor; emissions buffered in smem, ONE global atomic per block.
// Valid because classprobs <= 1 => fl(p*conf) <= conf, so score>0.9 => conf>0.9.
__global__ void k_scan(const float* __restrict__ preds) {
    __shared__ int                s_hot[256];
    __shared__ float              s_conf[256];
    __shared__ unsigned           s_n;
    __shared__ unsigned long long s_buf[SBUF];
    __shared__ unsigned           s_cnt, s_base, s_bufn;
    int img = blockIdx.y;
    int a   = blockIdx.x * 256 + threadIdx.x;
    if (threadIdx.x == 0) { s_n = 0; s_cnt = 0; }
    __syncthreads();
    float conf = 0.0f;
    if (a < NA) conf = __ldg(preds + ((size_t)img * NA + a) * NCH + 4);
    if (conf > 0.9f) {
        unsigned p = atomicAdd(&s_n, 1u);
        s_hot[p]  = a;
        s_conf[p] = conf;
    }
    __syncthreads();
    int nhot = (int)s_n;
    int wid  = threadIdx.x >> 5, lane = threadIdx.x & 31;
    for (int h = wid; h < nhot; h += 8) {
        int   aa = s_hot[h];
        float cf = s_conf[h];
        const float* pp = preds + ((size_t)img * NA + aa) * NCH + 5;
        float p0 = __ldg(pp + lane);
        float p1 = __ldg(pp + lane + 32);
        float p2 = (lane < 16) ? __ldg(pp + lane + 64) : 0.0f;
        float s0 = p0 * cf, s1 = p1 * cf, s2 = p2 * cf;
        bool e0 = s0 > 0.9f, e1 = s1 > 0.9f, e2 = s2 > 0.9f;
        unsigned b0 = __ballot_sync(0xFFFFFFFFu, e0);
        unsigned b1 = __ballot_sync(0xFFFFFFFFu, e1);
        unsigned b2 = __ballot_sync(0xFFFFFFFFu, e2);
        unsigned tot = __popc(b0) + __popc(b1) + __popc(b2);
        if (tot) {
            unsigned base = 0;
            if (lane == 0) base = atomicAdd(&s_cnt, tot);
            base = __shfl_sync(0xFFFFFFFFu, base, 0);
            unsigned lt = (1u << lane) - 1u;
            unsigned fb = (unsigned)aa * NCLS;
            unsigned o1 = __popc(b0), o2 = o1 + __popc(b1);
            #pragma unroll
            for (int t = 0; t < 3; t++) {
                bool  e    = (t == 0) ? e0 : (t == 1) ? e1 : e2;
                if (!e) continue;
                float sv   = (t == 0) ? s0 : (t == 1) ? s1 : s2;
                unsigned bt = (t == 0) ? b0 : (t == 1) ? b1 : b2;
                unsigned of = (t == 0) ? 0u : (t == 1) ? o1 : o2;
                unsigned cl = lane + 32u * t;
                unsigned bits = __float_as_uint(sv);
                unsigned bin  = (bits - (B09 + 1u)) >> 8; if (bin > NBINS - 1) bin = NBINS - 1;
                atomicAdd(&g_hist[img][bin], 1u);
                unsigned long long key = ((unsigned long long)bits << 32) |
                    (unsigned long long)(0xFFFFFFFFu - (fb + cl));
                unsigned slot = base + of + __popc(bt & lt);
                if (slot < SBUF) s_buf[slot] = key;
                else {
                    unsigned g = atomicAdd(&g_candcnt[img], 1u);
                    if (g < CAP) g_cand[img][g] = key;
                }
            }
        }
    }
    __syncthreads();
    if (threadIdx.x == 0) {
        unsigned bufn = s_cnt < SBUF ? s_cnt : SBUF;
        s_bufn = bufn;
        s_base = bufn ? atomicAdd(&g_candcnt[img], bufn) : 0u;
    }
    __syncthreads();
    unsigned bufn = s_bufn, gb = s_base;
    for (unsigned i = threadIdx.x; i < bufn; i += 256) {
        unsigned g = gb + i;
        if (g < CAP) g_cand[img][g] = s_buf[i];
    }
}

// ---------------------------------------------------------------- everything else, fused
// dyn smem: [0,128000) smask; aliased early as hist (32KB) then keys (32KB)
__global__ void __launch_bounds__(1024, 1) k_all(const float* __restrict__ preds,
                                                 float* __restrict__ dout) {
    extern __shared__ unsigned char dyn[];
    unsigned*           smask = (unsigned*)dyn;                 // PRE*32 words
    unsigned*           sh    = (unsigned*)dyn;                 // NBINS (early alias)
    unsigned long long* keys  = (unsigned long long*)dyn;       // SORTN (early alias)
    __shared__ unsigned csum[256];
    __shared__ int      s_fb;
    __shared__ unsigned s_thr;
    __shared__ unsigned scnt;
    __shared__ float    wmax[32];
    __shared__ float    s_maxv;
    __shared__ float4   sb[PADN];     // shifted boxes
    __shared__ float4   sbx[PADN];    // raw boxes
    __shared__ float    sa[PADN];
    __shared__ float    ssc[PADN];
    __shared__ int      sl[PADN];
    __shared__ unsigned slb[NCLS][32];
    int img = blockIdx.x, tid = threadIdx.x;

    // ---- threshold from fine hist ----
    for (int i = tid; i < NBINS; i += 1024) sh[i] = g_hist[img][i];
    __syncthreads();
    if (tid < 256) {
        unsigned ssum = 0;
        for (int j = 0; j < 32; j++) ssum += sh[tid * 32 + j];
        csum[tid] = ssum;
    }
    __syncthreads();
    if (tid == 0) {
        unsigned total = 0;
        for (int c = 0; c < 256; c++) total += csum[c];
        if (total >= PRE) {
            unsigned acc = 0, M = 0;
            int bstar = 0;
            for (int c = 255; c >= 0; c--) {
                if (acc + csum[c] >= PRE) {
                    for (int b = c * 32 + 31; b >= c * 32; b--) {
                        acc += sh[b];
                        if (acc >= PRE) { bstar = b; M = acc; break; }
                    }
                    break;
                }
                acc += csum[c];
            }
            if (M > SORTN) bstar++;                    // pathological ties
            s_thr = B09 + 1u + ((unsigned)bstar << 8);
            s_fb  = 0;
        } else {
            g_candcnt[img] = 0u;
            s_fb = 1;
        }
    }
    __syncthreads();

    // ---- fallback (rare): full-range in-block histogram + re-compact ----
    if (s_fb) {
        for (int i = tid; i < NBINS; i += 1024) sh[i] = 0u;
        __syncthreads();
        const float* base = preds + (size_t)img * NA * NCH;
        for (int a = tid; a < NA; a += 1024) {
            const float* p = base + (size_t)a * NCH;
            float conf = p[4];
            for (int c = 0; c < NCLS; c++) {
                float s = p[5 + c] * conf;
                if (s > CONF_TH) {
                    unsigned bin = __float_as_uint(s) >> 13;
                    if (bin > NBINS - 1) bin = NBINS - 1;
                    atomicAdd(&sh[bin], 1u);
                }
            }
        }
        __syncthreads();
        if (tid < 256) {
            unsigned ssum = 0;
            for (int j = 0; j < 32; j++) ssum += sh[tid * 32 + j];
            csum[tid] = ssum;
        }
        __syncthreads();
        if (tid == 0) {
            unsigned total = 0;
            for (int c = 0; c < 256; c++) total += csum[c];
            unsigned thr = 0;
            if (total >= PRE) {
                unsigned acc = 0, M = 0;
                int bstar = 0;
                for (int c = 255; c >= 0; c--) {
                    if (acc + csum[c] >= PRE) {
                        for (int b = c * 32 + 31; b >= c * 32; b--) {
                            acc += sh[b];
                            if (acc >= PRE) { bstar = b; M = acc; break; }
                        }
                        break;
                    }
                    acc += csum[c];
                }
                if (M > SORTN) bstar++;
                thr = (unsigned)bstar << 13;
            }
            s_thr = thr;
        }
        __syncthreads();
        unsigned thr = s_thr;
        for (int a = tid; a < NA; a += 1024) {
            const float* p = base + (size_t)a * NCH;
            float conf = p[4];
            unsigned fb = (unsigned)a * NCLS;
            for (int c = 0; c < NCLS; c++) {
                float s = p[5 + c] * conf;
                if (s > CONF_TH) {
                    unsigned bits = __float_as_uint(s);
                    if (bits >= thr) {
                        unsigned pos = atomicAdd(&g_candcnt[img], 1u);
                        if (pos < CAP)
                            g_cand[img][pos] = ((unsigned long long)bits << 32) |
                                (unsigned long long)(0xFFFFFFFFu - (fb + (unsigned)c));
                    }
                }
            }
        }
        __syncthreads();
    }

    // ---- compact candidates >= thr into keys (warp-aggregated) ----
    unsigned thr = s_thr;
    unsigned n   = g_candcnt[img]; if (n > CAP) n = CAP;
    if (tid == 0) scnt = 0;
    __syncthreads();                                   // sh dead -> keys live
    for (int i = tid; i < SORTN; i += 1024) keys[i] = 0ULL;
    for (int i = tid; i < NCLS * 32; i += 1024) (&slb[0][0])[i] = 0u;
    __syncthreads();
    unsigned nround = (n + 1023u) & ~1023u;            // FIX: was mis-parenthesized
    for (unsigned i = tid; i < nround; i += 1024) {
        unsigned long long k = 0ULL;
        bool ok = false;
        if (i < n) {
            k = g_cand[img][i];
            ok = (unsigned)(k >> 32) >= thr;
        }
        unsigned bal = __ballot_sync(0xFFFFFFFFu, ok);
        if (bal) {
            unsigned cnt = __popc(bal);
            unsigned base = 0;
            if ((tid & 31) == 0) base = atomicAdd(&scnt, cnt);
            base = __shfl_sync(0xFFFFFFFFu, base, 0);
            if (ok) {
                unsigned pos = base + __popc(bal & ((1u << (tid & 31)) - 1u));
                if (pos < SORTN) keys[pos] = k;
            }
        }
    }
    __syncthreads();

    // ---- sort descending ----
    if (scnt <= 1024u) {
        unsigned long long x = keys[tid];
        for (int k2 = 2; k2 <= 1024; k2 <<= 1) {
            bool up = (tid & k2) != 0;
            for (int j = k2 >> 1; j >= 32; j >>= 1) {
                unsigned long long y = keys[tid ^ j];
                bool isLo = (tid & j) == 0;
                bool takeMin = isLo ? up : !up;
                unsigned long long nx = takeMin ? (x < y ? x : y) : (x > y ? x : y);
                __syncthreads();
                keys[tid] = nx; x = nx;
                __syncthreads();
            }
            int j0 = ((k2 >> 1) < 16) ? (k2 >> 1) : 16;
            for (int j = j0; j >= 1; j >>= 1) {
                unsigned long long y = __shfl_xor_sync(0xFFFFFFFFu, x, j);
                bool isLo = (tid & j) == 0;
                bool takeMin = isLo ? up : !up;
                x = takeMin ? (x < y ? x : y) : (x > y ? x : y);
            }
            keys[tid] = x;
            __syncthreads();
        }
    } else {
        int n2 = (scnt <= 2048u) ? 2048 : SORTN;
        for (int k2 = 2; k2 <= n2; k2 <<= 1)
            for (int j = k2 >> 1; j > 0; j >>= 1) {
                for (int idx = tid; idx < n2; idx += 1024) {
                    int ixj = idx ^ j;
                    if (ixj > idx) {
                        unsigned long long x = keys[idx], y = keys[ixj];
                        bool asc  = (idx & k2) != 0;
                        bool sw   = asc ? (x > y) : (x < y);
                        if (sw) { keys[idx] = y; keys[ixj] = x; }
                    }
                }
                __syncthreads();
            }
    }

    // ---- decode + gather boxes ----
    float bx0 = 0.f, bx1 = 0.f, bx2 = 0.f, bx3 = 0.f, s = 0.f;
    int lab = 0;
    float localmax = 0.0f;
    {
        unsigned long long k = (tid < PRE) ? keys[tid] : 0ULL;
        if (k != 0ULL) {
            unsigned bits = (unsigned)(k >> 32);
            s = __uint_as_float(bits);
            unsigned flat = 0xFFFFFFFFu - (unsigned)(k & 0xFFFFFFFFull);
            int anc = (int)(flat / NCLS);
            lab     = (int)(flat % NCLS);
            const float* bp = preds + ((size_t)(img * NA + anc)) * NCH;
            bx0 = bp[0]; bx1 = bp[1]; bx2 = bp[2]; bx3 = bp[3];
        }
        localmax = fmaxf(fmaxf(bx0, bx1), fmaxf(bx2, bx3));
        ssc[tid] = s;
        sl[tid]  = lab;
        sbx[tid] = make_float4(bx0, bx1, bx2, bx3);
        if (tid < PRE)
            atomicOr(&slb[lab][tid >> 5], 1u << (tid & 31));
    }
    for (int o = 16; o; o >>= 1) localmax = fmaxf(localmax, __shfl_xor_sync(0xFFFFFFFFu, localmax, o));
    if ((tid & 31) == 0) wmax[tid >> 5] = localmax;
    __syncthreads();
    if (tid < 32) {
        float v = wmax[tid];
        for (int o = 16; o; o >>= 1) v = fmaxf(v, __shfl_xor_sync(0xFFFFFFFFu, v, o));
        if (tid == 0) s_maxv = v;
    }
    __syncthreads();
    float maxv = s_maxv;
    {
        float shift = (float)lab * (maxv + 1.0f);
        float x1 = bx0 + shift, y1 = bx1 + shift, x2 = bx2 + shift, y2 = bx3 + shift;
        sb[tid] = make_float4(x1, y1, x2, y2);
        sa[tid] = fmaxf(x2 - x1, 0.0f) * fmaxf(y2 - y1, 0.0f);
    }
    __syncthreads();                                   // keys dead -> smask live

    // ---- per-row suppression masks (same-label pairs only) ----
    if (tid < PRE) {
        int i = tid;
        int l = sl[i];
        float4 bi = sb[i];
        float  ai = sa[i];
        int wi = i >> 5;
        for (int w = 0; w < 32; w++) {
            unsigned word = 0u;
            if (w >= wi) {
                unsigned cand = slb[l][w];
                if (w == wi) cand &= ~((2u << (i & 31)) - 1u);
                while (cand) {
                    int bb = __ffs(cand) - 1; cand &= cand - 1;
                    int j = w * 32 + bb;
                    float4 bj = sb[j];
                    float ix1 = fmaxf(bi.x, bj.x), iy1 = fmaxf(bi.y, bj.y);
                    float ix2 = fminf(bi.z, bj.z), iy2 = fminf(bi.w, bj.w);
                    float inter = fmaxf(ix2 - ix1, 0.0f) * fmaxf(iy2 - iy1, 0.0f);
                    float den = ai + sa[j];
                    den = den - inter;
                    den = den + 1e-7f;
                    float iou = __fdiv_rn(inter, den);
                    if (iou > NMS_TH) word |= (1u << bb);
                }
            }
            smask[i * 32 + w] = word;
        }
    }
    __syncthreads();

    // ---- serial greedy NMS (one warp) + ordered output ----
    if (tid < 32) {
        int w = tid;
        unsigned valid = 0u;
        for (int b = 0; b < 32; b++) {
            int i = w * 32 + b;
            if (i < PRE && ssc[i] > CONF_TH) valid |= (1u << b);
        }
        unsigned removed = 0u, mykeep = 0u;
        for (int W = 0; W < 32; W++) {
            unsigned kw = 0u;
            if (w == W) {
                unsigned rW = removed;
                unsigned m = valid & ~rW;
                while (m) {
                    int b = __ffs(m) - 1;
                    kw |= (1u << b);
                    rW |= smask[(W * 32 + b) * 32 + W];
                    m &= ~rW;
                    m &= ~((2u << b) - 1u);
                }
                removed = rW;
            }
            kw = __shfl_sync(0xFFFFFFFFu, kw, W);
            unsigned m2 = kw;
            while (m2) {
                int b = __ffs(m2) - 1; m2 &= m2 - 1;
                removed |= smask[(W * 32 + b) * 32 + w];
            }
            if (w == W) mykeep = kw;
            __syncwarp();
        }
        int cnt = __popc(mykeep);
        int pre = cnt;
        for (int o = 1; o < 32; o <<= 1) {
            int v = __shfl_up_sync(0xFFFFFFFFu, pre, o);
            if (w >= o) pre += v;
        }
        int total = __shfl_sync(0xFFFFFFFFu, pre, 31);
        pre -= cnt;
        float* ob = dout + (size_t)img * MAXDET * 4;
        float* os = dout + (size_t)NB_IMG * MAXDET * 4 + (size_t)img * MAXDET;
        float* ol = dout + (size_t)NB_IMG * MAXDET * 5 + (size_t)img * MAXDET;
        unsigned m = mykeep;
        int r = pre;
        while (m) {
            int b = __ffs(m) - 1; m &= m - 1;
            if (r < MAXDET) {
                int i = w * 32 + b;
                float4 bx = sbx[i];
                ob[r * 4 + 0] = bx.x;
                ob[r * 4 + 1] = bx.y;
                ob[r * 4 + 2] = bx.z;
                ob[r * 4 + 3] = bx.w;
                os[r] = ssc[i];
                ol[r] = (float)sl[i];
            }
            r++;
        }
        for (int r2 = total + w; r2 < MAXDET; r2 += 32) {
            ob[r2 * 4 + 0] = 0.0f; ob[r2 * 4 + 1] = 0.0f;
            ob[r2 * 4 + 2] = 0.0f; ob[r2 * 4 + 3] = 0.0f;
            os[r2] = 0.0f;
            ol[r2] = -1.0f;
        }
    }

    // ---- restore zeroed state for next replay ----
    __syncthreads();
    for (int i = tid; i < NBINS; i += 1024) g_hist[img][i] = 0u;
    if (tid == 0) g_candcnt[img] = 0u;
}

// ---------------------------------------------------------------- launch
extern "C" void kernel_launch(void* const* d_in, const int* in_sizes, int n_in,
                              void* d_out, int out_size) {
    (void)in_sizes; (void)n_in; (void)out_size;
    const float* preds = (const float*)d_in[0];
    float* out = (float*)d_out;

    cudaFuncSetAttribute(k_all, cudaFuncAttributeMaxDynamicSharedMemorySize, 160 * 1024);

    k_scan<<<dim3((NA + 255) / 256, NB_IMG), 256>>>(preds);
    k_all<<<NB_IMG, 1024, PRE * 32 * sizeof(unsigned)>>>(preds, out);
}

// round 12
// speedup vs baseline: 1.0130x; 1.0130x over previous
#include <cuda_runtime.h>
#include <cstdint>

#define NB_IMG   16
#define NA       22743
#define NCH      85
#define NCLS     80
#define PRE      1000
#define PADN     1024
#define SORTN    4096
#define CAP      32768
#define NBINS    8192
#define MAXDET   300
#define CONF_TH  0.2f
#define NMS_TH   0.45f
#define SBUF     2048
#define MST      33            // padded smask row stride (words), conflict-free

static __device__ __constant__ unsigned B09 = 0x3F666666u; // bits(0.9f)

__device__ unsigned            g_hist[NB_IMG][NBINS];     // zero-init; re-zeroed by k_all
__device__ unsigned            g_candcnt[NB_IMG];         // idem
__device__ unsigned long long  g_cand[NB_IMG][CAP];

// ---------------------------------------------------------------- scan
// Phase A: block-compact hot anchors (conf>0.9).  Phase B: one warp per hot
// anchor; emissions buffered in smem, ONE global atomic per block.
// Valid because classprobs <= 1 => fl(p*conf) <= conf, so score>0.9 => conf>0.9.
__global__ void k_scan(const float* __restrict__ preds) {
    __shared__ int                s_hot[256];
    __shared__ float              s_conf[256];
    __shared__ unsigned           s_n;
    __shared__ unsigned long long s_buf[SBUF];
    __shared__ unsigned           s_cnt, s_base, s_bufn;
    int img = blockIdx.y;
    int a   = blockIdx.x * 256 + threadIdx.x;
    if (threadIdx.x == 0) { s_n = 0; s_cnt = 0; }
    __syncthreads();
    float conf = 0.0f;
    if (a < NA) conf = __ldg(preds + ((size_t)img * NA + a) * NCH + 4);
    if (conf > 0.9f) {
        unsigned p = atomicAdd(&s_n, 1u);
        s_hot[p]  = a;
        s_conf[p] = conf;
    }
    __syncthreads();
    int nhot = (int)s_n;
    int wid  = threadIdx.x >> 5, lane = threadIdx.x & 31;
    for (int h = wid; h < nhot; h += 8) {
        int   aa = s_hot[h];
        float cf = s_conf[h];
        const float* pp = preds + ((size_t)img * NA + aa) * NCH + 5;
        float p0 = __ldg(pp + lane);
        float p1 = __ldg(pp + lane + 32);
        float p2 = (lane < 16) ? __ldg(pp + lane + 64) : 0.0f;
        float s0 = p0 * cf, s1 = p1 * cf, s2 = p2 * cf;
        bool e0 = s0 > 0.9f, e1 = s1 > 0.9f, e2 = s2 > 0.9f;
        unsigned b0 = __ballot_sync(0xFFFFFFFFu, e0);
        unsigned b1 = __ballot_sync(0xFFFFFFFFu, e1);
        unsigned b2 = __ballot_sync(0xFFFFFFFFu, e2);
        unsigned tot = __popc(b0) + __popc(b1) + __popc(b2);
        if (tot) {
            unsigned base = 0;
            if (lane == 0) base = atomicAdd(&s_cnt, tot);
            base = __shfl_sync(0xFFFFFFFFu, base, 0);
            unsigned lt = (1u << lane) - 1u;
            unsigned fb = (unsigned)aa * NCLS;
            unsigned o1 = __popc(b0), o2 = o1 + __popc(b1);
            #pragma unroll
            for (int t = 0; t < 3; t++) {
                bool  e    = (t == 0) ? e0 : (t == 1) ? e1 : e2;
                if (!e) continue;
                float sv   = (t == 0) ? s0 : (t == 1) ? s1 : s2;
                unsigned bt = (t == 0) ? b0 : (t == 1) ? b1 : b2;
                unsigned of = (t == 0) ? 0u : (t == 1) ? o1 : o2;
                unsigned cl = lane + 32u * t;
                unsigned bits = __float_as_uint(sv);
                unsigned bin  = (bits - (B09 + 1u)) >> 8; if (bin > NBINS - 1) bin = NBINS - 1;
                atomicAdd(&g_hist[img][bin], 1u);
                unsigned long long key = ((unsigned long long)bits << 32) |
                    (unsigned long long)(0xFFFFFFFFu - (fb + cl));
                unsigned slot = base + of + __popc(bt & lt);
                if (slot < SBUF) s_buf[slot] = key;
                else {
                    unsigned g = atomicAdd(&g_candcnt[img], 1u);
                    if (g < CAP) g_cand[img][g] = key;
                }
            }
        }
    }
    __syncthreads();
    if (threadIdx.x == 0) {
        unsigned bufn = s_cnt < SBUF ? s_cnt : SBUF;
        s_bufn = bufn;
        s_base = bufn ? atomicAdd(&g_candcnt[img], bufn) : 0u;
    }
    __syncthreads();
    unsigned bufn = s_bufn, gb = s_base;
    for (unsigned i = threadIdx.x; i < bufn; i += 256) {
        unsigned g = gb + i;
        if (g < CAP) g_cand[img][g] = s_buf[i];
    }
}

// ---------------------------------------------------------------- everything else, fused
// dyn smem: [0,132000) smask (stride 33); aliased early as hist/keys (32KB)
__global__ void __launch_bounds__(1024, 1) k_all(const float* __restrict__ preds,
                                                 float* __restrict__ dout) {
    extern __shared__ unsigned char dyn[];
    unsigned*           smask = (unsigned*)dyn;                 // PRE*MST words
    unsigned*           sh    = (unsigned*)dyn;                 // NBINS (early alias)
    unsigned long long* keys  = (unsigned long long*)dyn;       // SORTN (early alias)
    __shared__ unsigned csum[256];
    __shared__ int      s_fb;
    __shared__ unsigned s_thr;
    __shared__ unsigned scnt;
    __shared__ float    wmax[32];
    __shared__ float    s_maxv;
    __shared__ float4   sb[PADN];     // shifted boxes
    __shared__ float4   sbx[PADN];    // raw boxes
    __shared__ float    sa[PADN];
    __shared__ float    ssc[PADN];
    __shared__ int      sl[PADN];
    __shared__ unsigned short csr[PADN];
    __shared__ unsigned lcnt[NCLS], loff[NCLS], lfill[NCLS];
    int img = blockIdx.x, tid = threadIdx.x;

    // ---- threshold from fine hist ----
    for (int i = tid; i < NBINS; i += 1024) sh[i] = g_hist[img][i];
    __syncthreads();
    if (tid < 256) {
        unsigned ssum = 0;
        for (int j = 0; j < 32; j++) ssum += sh[tid * 32 + j];
        csum[tid] = ssum;
    }
    __syncthreads();
    if (tid == 0) {
        unsigned total = 0;
        for (int c = 0; c < 256; c++) total += csum[c];
        if (total >= PRE) {
            unsigned acc = 0, M = 0;
            int bstar = 0;
            for (int c = 255; c >= 0; c--) {
                if (acc + csum[c] >= PRE) {
                    for (int b = c * 32 + 31; b >= c * 32; b--) {
                        acc += sh[b];
                        if (acc >= PRE) { bstar = b; M = acc; break; }
                    }
                    break;
                }
                acc += csum[c];
            }
            if (M > SORTN) bstar++;                    // pathological ties
            s_thr = B09 + 1u + ((unsigned)bstar << 8);
            s_fb  = 0;
        } else {
            g_candcnt[img] = 0u;
            s_fb = 1;
        }
    }
    __syncthreads();

    // ---- fallback (rare): full-range in-block histogram + re-compact ----
    if (s_fb) {
        for (int i = tid; i < NBINS; i += 1024) sh[i] = 0u;
        __syncthreads();
        const float* base = preds + (size_t)img * NA * NCH;
        for (int a = tid; a < NA; a += 1024) {
            const float* p = base + (size_t)a * NCH;
            float conf = p[4];
            for (int c = 0; c < NCLS; c++) {
                float s = p[5 + c] * conf;
                if (s > CONF_TH) {
                    unsigned bin = __float_as_uint(s) >> 13;
                    if (bin > NBINS - 1) bin = NBINS - 1;
                    atomicAdd(&sh[bin], 1u);
                }
            }
        }
        __syncthreads();
        if (tid < 256) {
            unsigned ssum = 0;
            for (int j = 0; j < 32; j++) ssum += sh[tid * 32 + j];
            csum[tid] = ssum;
        }
        __syncthreads();
        if (tid == 0) {
            unsigned total = 0;
            for (int c = 0; c < 256; c++) total += csum[c];
            unsigned thr = 0;
            if (total >= PRE) {
                unsigned acc = 0, M = 0;
                int bstar = 0;
                for (int c = 255; c >= 0; c--) {
                    if (acc + csum[c] >= PRE) {
                        for (int b = c * 32 + 31; b >= c * 32; b--) {
                            acc += sh[b];
                            if (acc >= PRE) { bstar = b; M = acc; break; }
                        }
                        break;
                    }
                    acc += csum[c];
                }
                if (M > SORTN) bstar++;
                thr = (unsigned)bstar << 13;
            }
            s_thr = thr;
        }
        __syncthreads();
        unsigned thr = s_thr;
        for (int a = tid; a < NA; a += 1024) {
            const float* p = base + (size_t)a * NCH;
            float conf = p[4];
            unsigned fb = (unsigned)a * NCLS;
            for (int c = 0; c < NCLS; c++) {
                float s = p[5 + c] * conf;
                if (s > CONF_TH) {
                    unsigned bits = __float_as_uint(s);
                    if (bits >= thr) {
                        unsigned pos = atomicAdd(&g_candcnt[img], 1u);
                        if (pos < CAP)
                            g_cand[img][pos] = ((unsigned long long)bits << 32) |
                                (unsigned long long)(0xFFFFFFFFu - (fb + (unsigned)c));
                    }
                }
            }
        }
        __syncthreads();
    }

    // ---- compact candidates >= thr into keys (warp-aggregated) ----
    unsigned thr = s_thr;
    unsigned n   = g_candcnt[img]; if (n > CAP) n = CAP;
    if (tid == 0) scnt = 0;
    __syncthreads();                                   // sh dead -> keys live
    for (int i = tid; i < SORTN; i += 1024) keys[i] = 0ULL;
    if (tid < NCLS) { lcnt[tid] = 0u; lfill[tid] = 0u; }
    __syncthreads();
    unsigned nround = (n + 1023u) & ~1023u;
    for (unsigned i = tid; i < nround; i += 1024) {
        unsigned long long k = 0ULL;
        bool ok = false;
        if (i < n) {
            k = g_cand[img][i];
            ok = (unsigned)(k >> 32) >= thr;
        }
        unsigned bal = __ballot_sync(0xFFFFFFFFu, ok);
        if (bal) {
            unsigned cnt = __popc(bal);
            unsigned base = 0;
            if ((tid & 31) == 0) base = atomicAdd(&scnt, cnt);
            base = __shfl_sync(0xFFFFFFFFu, base, 0);
            if (ok) {
                unsigned pos = base + __popc(bal & ((1u << (tid & 31)) - 1u));
                if (pos < SORTN) keys[pos] = k;
            }
        }
    }
    __syncthreads();

    // ---- sort descending ----
    if (scnt <= 1024u) {
        unsigned long long x = keys[tid];
        for (int k2 = 2; k2 <= 1024; k2 <<= 1) {
            bool up = (tid & k2) != 0;
            for (int j = k2 >> 1; j >= 32; j >>= 1) {
                unsigned long long y = keys[tid ^ j];
                bool isLo = (tid & j) == 0;
                bool takeMin = isLo ? up : !up;
                unsigned long long nx = takeMin ? (x < y ? x : y) : (x > y ? x : y);
                __syncthreads();
                keys[tid] = nx; x = nx;
                __syncthreads();
            }
            int j0 = ((k2 >> 1) < 16) ? (k2 >> 1) : 16;
            for (int j = j0; j >= 1; j >>= 1) {
                unsigned long long y = __shfl_xor_sync(0xFFFFFFFFu, x, j);
                bool isLo = (tid & j) == 0;
                bool takeMin = isLo ? up : !up;
                x = takeMin ? (x < y ? x : y) : (x > y ? x : y);
            }
            keys[tid] = x;
            __syncthreads();
        }
    } else {
        int n2 = (scnt <= 2048u) ? 2048 : SORTN;
        for (int k2 = 2; k2 <= n2; k2 <<= 1)
            for (int j = k2 >> 1; j > 0; j >>= 1) {
                for (int idx = tid; idx < n2; idx += 1024) {
                    int ixj = idx ^ j;
                    if (ixj > idx) {
                        unsigned long long x = keys[idx], y = keys[ixj];
                        bool asc  = (idx & k2) != 0;
                        bool sw   = asc ? (x > y) : (x < y);
                        if (sw) { keys[idx] = y; keys[ixj] = x; }
                    }
                }
                __syncthreads();
            }
    }

    // ---- decode + gather boxes ----
    float bx0 = 0.f, bx1 = 0.f, bx2 = 0.f, bx3 = 0.f, s = 0.f;
    int lab = 0;
    bool real = false;
    float localmax = 0.0f;
    {
        unsigned long long k = (tid < PRE) ? keys[tid] : 0ULL;
        if (k != 0ULL) {
            real = true;
            unsigned bits = (unsigned)(k >> 32);
            s = __uint_as_float(bits);
            unsigned flat = 0xFFFFFFFFu - (unsigned)(k & 0xFFFFFFFFull);
            int anc = (int)(flat / NCLS);
            lab     = (int)(flat % NCLS);
            const float* bp = preds + ((size_t)(img * NA + anc)) * NCH;
            bx0 = bp[0]; bx1 = bp[1]; bx2 = bp[2]; bx3 = bp[3];
            atomicAdd(&lcnt[lab], 1u);
        }
        localmax = fmaxf(fmaxf(bx0, bx1), fmaxf(bx2, bx3));
        ssc[tid] = s;
        sl[tid]  = lab;
        sbx[tid] = make_float4(bx0, bx1, bx2, bx3);
    }
    for (int o = 16; o; o >>= 1) localmax = fmaxf(localmax, __shfl_xor_sync(0xFFFFFFFFu, localmax, o));
    if ((tid & 31) == 0) wmax[tid >> 5] = localmax;
    __syncthreads();
    if (tid < 32) {
        float v = wmax[tid];
        for (int o = 16; o; o >>= 1) v = fmaxf(v, __shfl_xor_sync(0xFFFFFFFFu, v, o));
        if (tid == 0) s_maxv = v;
    }
    __syncthreads();
    float maxv = s_maxv;
    {
        float shift = (float)lab * (maxv + 1.0f);
        float x1 = bx0 + shift, y1 = bx1 + shift, x2 = bx2 + shift, y2 = bx3 + shift;
        sb[tid] = make_float4(x1, y1, x2, y2);
        sa[tid] = fmaxf(x2 - x1, 0.0f) * fmaxf(y2 - y1, 0.0f);
    }
    __syncthreads();                                   // keys dead -> smask live

    // ---- zero padded mask + CSR prefix ----
    for (int i = tid; i < PRE * MST; i += 1024) smask[i] = 0u;
    if (tid == 0) {
        unsigned off = 0;
        for (int l = 0; l < NCLS; l++) { loff[l] = off; off += lcnt[l]; }
    }
    __syncthreads();
    if (real) {
        unsigned pos = atomicAdd(&lfill[lab], 1u);
        csr[loff[lab] + pos] = (unsigned short)tid;
    }
    __syncthreads();

    // ---- same-label pair IoU -> suppression bits (warp per label) ----
    {
        int wld = tid >> 5, ln = tid & 31;
        for (int l = wld; l < NCLS; l += 32) {
            int m   = (int)lcnt[l];
            int off = (int)loff[l];
            for (int a = 0; a + 1 < m; a++) {
                int i0 = csr[off + a];
                float4 bi = sb[i0];
                float  ai = sa[i0];
                for (int b = a + 1 + ln; b < m; b += 32) {
                    int j0 = csr[off + b];
                    float4 bj = sb[j0];
                    float ix1 = fmaxf(bi.x, bj.x), iy1 = fmaxf(bi.y, bj.y);
                    float ix2 = fminf(bi.z, bj.z), iy2 = fminf(bi.w, bj.w);
                    float inter = fmaxf(ix2 - ix1, 0.0f) * fmaxf(iy2 - iy1, 0.0f);
                    float den = ai + sa[j0];
                    den = den - inter;
                    den = den + 1e-7f;
                    float iou = __fdiv_rn(inter, den);
                    if (iou > NMS_TH) {
                        int r = i0 < j0 ? i0 : j0;
                        int c = i0 < j0 ? j0 : i0;
                        atomicOr(&smask[r * MST + (c >> 5)], 1u << (c & 31));
                    }
                }
            }
        }
    }
    __syncthreads();

    // ---- serial greedy NMS (one warp) + ordered output ----
    if (tid < 32) {
        int w = tid;
        unsigned valid = 0u;
        for (int b = 0; b < 32; b++) {
            int i = w * 32 + b;
            if (i < PRE && ssc[i] > CONF_TH) valid |= (1u << b);
        }
        unsigned removed = 0u, mykeep = 0u;
        for (int W = 0; W < 32; W++) {
            unsigned kw = 0u;
            if (w == W) {
                unsigned rW = removed;
                unsigned m = valid & ~rW;
                while (m) {
                    int b = __ffs(m) - 1;
                    kw |= (1u << b);
                    rW |= smask[(W * 32 + b) * MST + W];
                    m &= ~rW;
                    m &= ~((2u << b) - 1u);
                }
                removed = rW;
            }
            kw = __shfl_sync(0xFFFFFFFFu, kw, W);
            unsigned m2 = kw;
            while (m2) {
                int b = __ffs(m2) - 1; m2 &= m2 - 1;
                removed |= smask[(W * 32 + b) * MST + w];
            }
            if (w == W) mykeep = kw;
            __syncwarp();
        }
        int cnt = __popc(mykeep);
        int pre = cnt;
        for (int o = 1; o < 32; o <<= 1) {
            int v = __shfl_up_sync(0xFFFFFFFFu, pre, o);
            if (w >= o) pre += v;
        }
        int total = __shfl_sync(0xFFFFFFFFu, pre, 31);
        pre -= cnt;
        float* ob = dout + (size_t)img * MAXDET * 4;
        float* os = dout + (size_t)NB_IMG * MAXDET * 4 + (size_t)img * MAXDET;
        float* ol = dout + (size_t)NB_IMG * MAXDET * 5 + (size_t)img * MAXDET;
        unsigned m = mykeep;
        int r = pre;
        while (m) {
            int b = __ffs(m) - 1; m &= m - 1;
            if (r < MAXDET) {
                int i = w * 32 + b;
                float4 bx = sbx[i];
                ob[r * 4 + 0] = bx.x;
                ob[r * 4 + 1] = bx.y;
                ob[r * 4 + 2] = bx.z;
                ob[r * 4 + 3] = bx.w;
                os[r] = ssc[i];
                ol[r] = (float)sl[i];
            }
            r++;
        }
        for (int r2 = total + w; r2 < MAXDET; r2 += 32) {
            ob[r2 * 4 + 0] = 0.0f; ob[r2 * 4 + 1] = 0.0f;
            ob[r2 * 4 + 2] = 0.0f; ob[r2 * 4 + 3] = 0.0f;
            os[r2] = 0.0f;
            ol[r2] = -1.0f;
        }
    }

    // ---- restore zeroed state for next replay ----
    __syncthreads();
    for (int i = tid; i < NBINS; i += 1024) g_hist[img][i] = 0u;
    if (tid == 0) g_candcnt[img] = 0u;
}

// ---------------------------------------------------------------- launch
extern "C" void kernel_launch(void* const* d_in, const int* in_sizes, int n_in,
                              void* d_out, int out_size) {
    (void)in_sizes; (void)n_in; (void)out_size;
    const float* preds = (const float*)d_in[0];
    float* out = (float*)d_out;

    cudaFuncSetAttribute(k_all, cudaFuncAttributeMaxDynamicSharedMemorySize, 160 * 1024);

    k_scan<<<dim3((NA + 255) / 256, NB_IMG), 256>>>(preds);
    k_all<<<NB_IMG, 1024, PRE * MST * sizeof(unsigned)>>>(preds, out);
}

// round 16
// speedup vs baseline: 1.6040x; 1.5834x over previous
#include <cuda_runtime.h>
#include <cstdint>

#define NB_IMG   16
#define NA       22743
#define NCH      85
#define NCLS     80
#define PRE      1000
#define PADN     1024
#define SORTN    4096
#define CAP      32768
#define NBINS    8192
#define MAXDET   300
#define CONF_TH  0.2f
#define NMS_TH   0.45f
#define SBUF     2048
#define MST      33            // padded smask row stride (words), conflict-free

static __device__ __constant__ unsigned B09 = 0x3F666666u; // bits(0.9f)

__device__ unsigned            g_hist[NB_IMG][NBINS];     // zero-init; re-zeroed by k_all
__device__ unsigned            g_candcnt[NB_IMG];         // idem
__device__ unsigned long long  g_cand[NB_IMG][CAP];

// ---------------------------------------------------------------- scan
// Phase A: block-compact hot anchors (conf>0.9).  Phase B: one warp per hot
// anchor; emissions buffered in smem, ONE global atomic per block.
// Valid because classprobs <= 1 => fl(p*conf) <= conf, so score>0.9 => conf>0.9.
__global__ void k_scan(const float* __restrict__ preds) {
    __shared__ int                s_hot[256];
    __shared__ float              s_conf[256];
    __shared__ unsigned           s_n;
    __shared__ unsigned long long s_buf[SBUF];
    __shared__ unsigned           s_cnt, s_base, s_bufn;
    int img = blockIdx.y;
    int a   = blockIdx.x * 256 + threadIdx.x;
    if (threadIdx.x == 0) { s_n = 0; s_cnt = 0; }
    __syncthreads();
    float conf = 0.0f;
    if (a < NA) conf = __ldg(preds + ((size_t)img * NA + a) * NCH + 4);
    if (conf > 0.9f) {
        unsigned p = atomicAdd(&s_n, 1u);
        s_hot[p]  = a;
        s_conf[p] = conf;
    }
    __syncthreads();
    int nhot = (int)s_n;
    int wid  = threadIdx.x >> 5, lane = threadIdx.x & 31;
    for (int h = wid; h < nhot; h += 8) {
        int   aa = s_hot[h];
        float cf = s_conf[h];
        const float* pp = preds + ((size_t)img * NA + aa) * NCH + 5;
        float p0 = __ldg(pp + lane);
        float p1 = __ldg(pp + lane + 32);
        float p2 = (lane < 16) ? __ldg(pp + lane + 64) : 0.0f;
        float s0 = p0 * cf, s1 = p1 * cf, s2 = p2 * cf;
        bool e0 = s0 > 0.9f, e1 = s1 > 0.9f, e2 = s2 > 0.9f;
        unsigned b0 = __ballot_sync(0xFFFFFFFFu, e0);
        unsigned b1 = __ballot_sync(0xFFFFFFFFu, e1);
        unsigned b2 = __ballot_sync(0xFFFFFFFFu, e2);
        unsigned tot = __popc(b0) + __popc(b1) + __popc(b2);
        if (tot) {
            unsigned base = 0;
            if (lane == 0) base = atomicAdd(&s_cnt, tot);
            base = __shfl_sync(0xFFFFFFFFu, base, 0);
            unsigned lt = (1u << lane) - 1u;
            unsigned fb = (unsigned)aa * NCLS;
            unsigned o1 = __popc(b0), o2 = o1 + __popc(b1);
            #pragma unroll
            for (int t = 0; t < 3; t++) {
                bool  e    = (t == 0) ? e0 : (t == 1) ? e1 : e2;
                if (!e) continue;
                float sv   = (t == 0) ? s0 : (t == 1) ? s1 : s2;
                unsigned bt = (t == 0) ? b0 : (t == 1) ? b1 : b2;
                unsigned of = (t == 0) ? 0u : (t == 1) ? o1 : o2;
                unsigned cl = lane + 32u * t;
                unsigned bits = __float_as_uint(sv);
                unsigned bin  = (bits - (B09 + 1u)) >> 8; if (bin > NBINS - 1) bin = NBINS - 1;
                atomicAdd(&g_hist[img][bin], 1u);
                unsigned long long key = ((unsigned long long)bits << 32) |
                    (unsigned long long)(0xFFFFFFFFu - (fb + cl));
                unsigned slot = base + of + __popc(bt & lt);
                if (slot < SBUF) s_buf[slot] = key;
                else {
                    unsigned g = atomicAdd(&g_candcnt[img], 1u);
                    if (g < CAP) g_cand[img][g] = key;
                }
            }
        }
    }
    __syncthreads();
    if (threadIdx.x == 0) {
        unsigned bufn = s_cnt < SBUF ? s_cnt : SBUF;
        s_bufn = bufn;
        s_base = bufn ? atomicAdd(&g_candcnt[img], bufn) : 0u;
    }
    __syncthreads();
    unsigned bufn = s_bufn, gb = s_base;
    for (unsigned i = threadIdx.x; i < bufn; i += 256) {
        unsigned g = gb + i;
        if (g < CAP) g_cand[img][g] = s_buf[i];
    }
}

// ---------------------------------------------------------------- everything else, fused
// dyn smem: [0,132000) smask (stride 33); aliased early as hist/keys (32KB)
__global__ void __launch_bounds__(1024, 1) k_all(const float* __restrict__ preds,
                                                 float* __restrict__ dout) {
    extern __shared__ unsigned char dyn[];
    unsigned*           smask = (unsigned*)dyn;                 // PRE*MST words
    unsigned*           sh    = (unsigned*)dyn;                 // NBINS (early alias)
    unsigned long long* keys  = (unsigned long long*)dyn;       // SORTN (early alias)
    __shared__ unsigned csum[256];
    __shared__ int      s_fb;
    __shared__ unsigned s_thr;
    __shared__ unsigned scnt;
    __shared__ float    wmax[32];
    __shared__ float    s_maxv;
    __shared__ float4   sb[PADN];     // shifted boxes
    __shared__ float4   sbx[PADN];    // raw boxes
    __shared__ float    sa[PADN];
    __shared__ float    ssc[PADN];
    __shared__ int      sl[PADN];
    __shared__ unsigned short csr[PADN];
    __shared__ unsigned lcnt[NCLS], loff[NCLS], lfill[NCLS];
    __shared__ unsigned nzrow[32];    // rows with nonzero suppression masks
    int img = blockIdx.x, tid = threadIdx.x;

    // ---- threshold from fine hist ----
    for (int i = tid; i < NBINS; i += 1024) sh[i] = g_hist[img][i];
    __syncthreads();
    if (tid < 256) {
        unsigned ssum = 0;
        for (int j = 0; j < 32; j++) ssum += sh[tid * 32 + j];
        csum[tid] = ssum;
    }
    __syncthreads();
    if (tid == 0) {
        unsigned total = 0;
        for (int c = 0; c < 256; c++) total += csum[c];
        if (total >= PRE) {
            unsigned acc = 0, M = 0;
            int bstar = 0;
            for (int c = 255; c >= 0; c--) {
                if (acc + csum[c] >= PRE) {
                    for (int b = c * 32 + 31; b >= c * 32; b--) {
                        acc += sh[b];
                        if (acc >= PRE) { bstar = b; M = acc; break; }
                    }
                    break;
                }
                acc += csum[c];
            }
            if (M > SORTN) bstar++;                    // pathological ties
            s_thr = B09 + 1u + ((unsigned)bstar << 8);
            s_fb  = 0;
        } else {
            g_candcnt[img] = 0u;
            s_fb = 1;
        }
    }
    __syncthreads();

    // ---- fallback (rare): full-range in-block histogram + re-compact ----
    if (s_fb) {
        for (int i = tid; i < NBINS; i += 1024) sh[i] = 0u;
        __syncthreads();
        const float* base = preds + (size_t)img * NA * NCH;
        for (int a = tid; a < NA; a += 1024) {
            const float* p = base + (size_t)a * NCH;
            float conf = p[4];
            for (int c = 0; c < NCLS; c++) {
                float s = p[5 + c] * conf;
                if (s > CONF_TH) {
                    unsigned bin = __float_as_uint(s) >> 13;
                    if (bin > NBINS - 1) bin = NBINS - 1;
                    atomicAdd(&sh[bin], 1u);
                }
            }
        }
        __syncthreads();
        if (tid < 256) {
            unsigned ssum = 0;
            for (int j = 0; j < 32; j++) ssum += sh[tid * 32 + j];
            csum[tid] = ssum;
        }
        __syncthreads();
        if (tid == 0) {
            unsigned total = 0;
            for (int c = 0; c < 256; c++) total += csum[c];
            unsigned thr = 0;
            if (total >= PRE) {
                unsigned acc = 0, M = 0;
                int bstar = 0;
                for (int c = 255; c >= 0; c--) {
                    if (acc + csum[c] >= PRE) {
                        for (int b = c * 32 + 31; b >= c * 32; b--) {
                            acc += sh[b];
                            if (acc >= PRE) { bstar = b; M = acc; break; }
                        }
                        break;
                    }
                    acc += csum[c];
                }
                if (M > SORTN) bstar++;
                thr = (unsigned)bstar << 13;
            }
            s_thr = thr;
        }
        __syncthreads();
        unsigned thr = s_thr;
        for (int a = tid; a < NA; a += 1024) {
            const float* p = base + (size_t)a * NCH;
            float conf = p[4];
            unsigned fb = (unsigned)a * NCLS;
            for (int c = 0; c < NCLS; c++) {
                float s = p[5 + c] * conf;
                if (s > CONF_TH) {
                    unsigned bits = __float_as_uint(s);
                    if (bits >= thr) {
                        unsigned pos = atomicAdd(&g_candcnt[img], 1u);
                        if (pos < CAP)
                            g_cand[img][pos] = ((unsigned long long)bits << 32) |
                                (unsigned long long)(0xFFFFFFFFu - (fb + (unsigned)c));
                    }
                }
            }
        }
        __syncthreads();
    }

    // ---- compact candidates >= thr into keys (warp-aggregated) ----
    unsigned thr = s_thr;
    unsigned n   = g_candcnt[img]; if (n > CAP) n = CAP;
    if (tid == 0) scnt = 0;
    __syncthreads();                                   // sh dead -> keys live
    for (int i = tid; i < SORTN; i += 1024) keys[i] = 0ULL;
    if (tid < NCLS) { lcnt[tid] = 0u; lfill[tid] = 0u; }
    if (tid < 32) nzrow[tid] = 0u;
    __syncthreads();
    unsigned nround = (n + 1023u) & ~1023u;
    for (unsigned i = tid; i < nround; i += 1024) {
        unsigned long long k = 0ULL;
        bool ok = false;
        if (i < n) {
            k = g_cand[img][i];
            ok = (unsigned)(k >> 32) >= thr;
        }
        unsigned bal = __ballot_sync(0xFFFFFFFFu, ok);
        if (bal) {
            unsigned cnt = __popc(bal);
            unsigned base = 0;
            if ((tid & 31) == 0) base = atomicAdd(&scnt, cnt);
            base = __shfl_sync(0xFFFFFFFFu, base, 0);
            if (ok) {
                unsigned pos = base + __popc(bal & ((1u << (tid & 31)) - 1u));
                if (pos < SORTN) keys[pos] = k;
            }
        }
    }
    __syncthreads();

    // ---- sort descending ----
    if (scnt <= 1024u) {
        unsigned long long x = keys[tid];
        for (int k2 = 2; k2 <= 1024; k2 <<= 1) {
            bool up = (tid & k2) != 0;
            for (int j = k2 >> 1; j >= 32; j >>= 1) {
                unsigned long long y = keys[tid ^ j];
                bool isLo = (tid & j) == 0;
                bool takeMin = isLo ? up : !up;
                unsigned long long nx = takeMin ? (x < y ? x : y) : (x > y ? x : y);
                __syncthreads();
                keys[tid] = nx; x = nx;
                __syncthreads();
            }
            int j0 = ((k2 >> 1) < 16) ? (k2 >> 1) : 16;
            for (int j = j0; j >= 1; j >>= 1) {
                unsigned long long y = __shfl_xor_sync(0xFFFFFFFFu, x, j);
                bool isLo = (tid & j) == 0;
                bool takeMin = isLo ? up : !up;
                x = takeMin ? (x < y ? x : y) : (x > y ? x : y);
            }
            keys[tid] = x;
            __syncthreads();
        }
    } else {
        int n2 = (scnt <= 2048u) ? 2048 : SORTN;
        for (int k2 = 2; k2 <= n2; k2 <<= 1)
            for (int j = k2 >> 1; j > 0; j >>= 1) {
                for (int idx = tid; idx < n2; idx += 1024) {
                    int ixj = idx ^ j;
                    if (ixj > idx) {
                        unsigned long long x = keys[idx], y = keys[ixj];
                        bool asc  = (idx & k2) != 0;
                        bool sw   = asc ? (x > y) : (x < y);
                        if (sw) { keys[idx] = y; keys[ixj] = x; }
                    }
                }
                __syncthreads();
            }
    }

    // ---- decode + gather boxes ----
    float bx0 = 0.f, bx1 = 0.f, bx2 = 0.f, bx3 = 0.f, s = 0.f;
    int lab = 0;
    bool real = false;
    float localmax = 0.0f;
    {
        unsigned long long k = (tid < PRE) ? keys[tid] : 0ULL;
        if (k != 0ULL) {
            real = true;
            unsigned bits = (unsigned)(k >> 32);
            s = __uint_as_float(bits);
            unsigned flat = 0xFFFFFFFFu - (unsigned)(k & 0xFFFFFFFFull);
            int anc = (int)(flat / NCLS);
            lab     = (int)(flat % NCLS);
            const float* bp = preds + ((size_t)(img * NA + anc)) * NCH;
            bx0 = bp[0]; bx1 = bp[1]; bx2 = bp[2]; bx3 = bp[3];
            atomicAdd(&lcnt[lab], 1u);
        }
        localmax = fmaxf(fmaxf(bx0, bx1), fmaxf(bx2, bx3));
        ssc[tid] = s;
        sl[tid]  = lab;
        sbx[tid] = make_float4(bx0, bx1, bx2, bx3);
    }
    for (int o = 16; o; o >>= 1) localmax = fmaxf(localmax, __shfl_xor_sync(0xFFFFFFFFu, localmax, o));
    if ((tid & 31) == 0) wmax[tid >> 5] = localmax;
    __syncthreads();
    if (tid < 32) {
        float v = wmax[tid];
        for (int o = 16; o; o >>= 1) v = fmaxf(v, __shfl_xor_sync(0xFFFFFFFFu, v, o));
        if (tid == 0) s_maxv = v;
    }
    __syncthreads();
    float maxv = s_maxv;
    {
        float shift = (float)lab * (maxv + 1.0f);
        float x1 = bx0 + shift, y1 = bx1 + shift, x2 = bx2 + shift, y2 = bx3 + shift;
        sb[tid] = make_float4(x1, y1, x2, y2);
        sa[tid] = fmaxf(x2 - x1, 0.0f) * fmaxf(y2 - y1, 0.0f);
    }
    __syncthreads();                                   // keys dead -> smask live

    // ---- zero padded mask + CSR prefix ----
    for (int i = tid; i < PRE * MST; i += 1024) smask[i] = 0u;
    if (tid == 0) {
        unsigned off = 0;
        for (int l = 0; l < NCLS; l++) { loff[l] = off; off += lcnt[l]; }
    }
    __syncthreads();
    if (real) {
        unsigned pos = atomicAdd(&lfill[lab], 1u);
        csr[loff[lab] + pos] = (unsigned short)tid;
    }
    __syncthreads();

    // ---- same-label pair IoU -> suppression bits (warp per label) ----
    {
        int wld = tid >> 5, ln = tid & 31;
        for (int l = wld; l < NCLS; l += 32) {
            int m   = (int)lcnt[l];
            int off = (int)loff[l];
            for (int a = 0; a + 1 < m; a++) {
                int i0 = csr[off + a];
                float4 bi = sb[i0];
                float  ai = sa[i0];
                for (int b = a + 1 + ln; b < m; b += 32) {
                    int j0 = csr[off + b];
                    float4 bj = sb[j0];
                    float ix1 = fmaxf(bi.x, bj.x), iy1 = fmaxf(bi.y, bj.y);
                    float ix2 = fminf(bi.z, bj.z), iy2 = fminf(bi.w, bj.w);
                    float inter = fmaxf(ix2 - ix1, 0.0f) * fmaxf(iy2 - iy1, 0.0f);
                    float den = ai + sa[j0];
                    den = den - inter;
                    den = den + 1e-7f;
                    float iou = __fdiv_rn(inter, den);
                    if (iou > NMS_TH) {
                        int r = i0 < j0 ? i0 : j0;
                        int c = i0 < j0 ? j0 : i0;
                        atomicOr(&smask[r * MST + (c >> 5)], 1u << (c & 31));
                        atomicOr(&nzrow[r >> 5], 1u << (r & 31));
                    }
                }
            }
        }
    }
    __syncthreads();

    // ---- sparse-chain greedy NMS (one warp) + ordered output ----
    // Masks are strictly upper-triangular (r<c): removed bit j is only ever set
    // by rows i<j, so zero-mask rows never change state and
    // keep[i] = valid[i] & ~removed_final[i] exactly, with removed built by
    // walking only nonzero-mask rows in index order.
    if (tid < 32) {
        int w = tid;
        unsigned valid = 0u;
        for (int b = 0; b < 32; b++) {
            int i = w * 32 + b;
            if (i < PRE && ssc[i] > CONF_TH) valid |= (1u << b);
        }
        unsigned removed = 0u;
        unsigned nzmine = nzrow[w];
        for (int W = 0; W < 32; W++) {
            unsigned nzW = __shfl_sync(0xFFFFFFFFu, nzmine, W);
            if (!nzW) continue;
            unsigned vW = __shfl_sync(0xFFFFFFFFu, valid, W);
            while (nzW) {
                int b = __ffs(nzW) - 1; nzW &= nzW - 1;
                unsigned rW = __shfl_sync(0xFFFFFFFFu, removed, W);
                if (((vW >> b) & 1u) && !((rW >> b) & 1u))
                    removed |= smask[(W * 32 + b) * MST + w];
            }
        }
        unsigned mykeep = valid & ~removed;

        int cnt = __popc(mykeep);
        int pre = cnt;
        for (int o = 1; o < 32; o <<= 1) {
            int v = __shfl_up_sync(0xFFFFFFFFu, pre, o);
            if (w >= o) pre += v;
        }
        int total = __shfl_sync(0xFFFFFFFFu, pre, 31);
        pre -= cnt;
        float* ob = dout + (size_t)img * MAXDET * 4;
        float* os = dout + (size_t)NB_IMG * MAXDET * 4 + (size_t)img * MAXDET;
        float* ol = dout + (size_t)NB_IMG * MAXDET * 5 + (size_t)img * MAXDET;
        unsigned m = mykeep;
        int r = pre;
        while (m) {
            int b = __ffs(m) - 1; m &= m - 1;
            if (r < MAXDET) {
                int i = w * 32 + b;
                float4 bx = sbx[i];
                ob[r * 4 + 0] = bx.x;
                ob[r * 4 + 1] = bx.y;
                ob[r * 4 + 2] = bx.z;
                ob[r * 4 + 3] = bx.w;
                os[r] = ssc[i];
                ol[r] = (float)sl[i];
            }
            r++;
        }
        for (int r2 = total + w; r2 < MAXDET; r2 += 32) {
            ob[r2 * 4 + 0] = 0.0f; ob[r2 * 4 + 1] = 0.0f;
            ob[r2 * 4 + 2] = 0.0f; ob[r2 * 4 + 3] = 0.0f;
            os[r2] = 0.0f;
            ol[r2] = -1.0f;
        }
    }

    // ---- restore zeroed state for next replay ----
    __syncthreads();
    for (int i = tid; i < NBINS; i += 1024) g_hist[img][i] = 0u;
    if (tid == 0) g_candcnt[img] = 0u;
}

// ---------------------------------------------------------------- launch
extern "C" void kernel_launch(void* const* d_in, const int* in_sizes, int n_in,
                              void* d_out, int out_size) {
    (void)in_sizes; (void)n_in; (void)out_size;
    const float* preds = (const float*)d_in[0];
    float* out = (float*)d_out;

    cudaFuncSetAttribute(k_all, cudaFuncAttributeMaxDynamicSharedMemorySize, 160 * 1024);

    k_scan<<<dim3((NA + 255) / 256, NB_IMG), 256>>>(preds);
    k_all<<<NB_IMG, 1024, PRE * MST * sizeof(unsigned)>>>(preds, out);
}